// round 9
// baseline (speedup 1.0000x reference)
#include <cuda_runtime.h>

// SU2Attention: batch=1, seq=2048, heads=8, spinor_dim=2 (complex).
// Per head: Q=K are 4-dim real unit vectors u_j = s_j/||s_j||, logits u_i.u_j
// scaled by 1/sqrt(2) (bounded -> no max subtraction), softmax over keys,
// values are raw 4-vectors s_j.
//
// Output layout (verified R5-R8): PLANAR — real plane (2048*8*2 floats) then
// imag plane. d_in[0]=real, d_in[1]=imag.
//
// R9: query-pair-packed f32x2 dots. Key unit vectors stored PRE-DUPLICATED in
// shared as (x,x,y,y),(z,z,w,w) so a pair of queries' dots is 4 packed FFMAs
// with no horizontal add and no per-key duplicate MOVs.
// Per key (4 queries/thread): fma-pipe ops 24 -> 20, LDS 2 -> 3.

#define SEQ    2048
#define HEADS  8
#define QTILE  128
#define NQ     4
#define BLOCK  1024
#define NWARP  (BLOCK / 32)         // 32 splits
#define JCHUNK (SEQ / NWARP)        // 64 keys per warp

typedef unsigned long long u64_t;

__device__ __forceinline__ float2 fmul2(float2 a, float2 b) {
    float2 d;
    asm("mul.rn.f32x2 %0, %1, %2;"
        : "=l"(reinterpret_cast<u64_t&>(d))
        : "l"(reinterpret_cast<const u64_t&>(a)),
          "l"(reinterpret_cast<const u64_t&>(b)));
    return d;
}

__device__ __forceinline__ float2 ffma2(float2 a, float2 b, float2 c) {
    float2 d;
    asm("fma.rn.f32x2 %0, %1, %2, %3;"
        : "=l"(reinterpret_cast<u64_t&>(d))
        : "l"(reinterpret_cast<const u64_t&>(a)),
          "l"(reinterpret_cast<const u64_t&>(b)),
          "l"(reinterpret_cast<const u64_t&>(c)));
    return d;
}

__device__ __forceinline__ float ex2_approx(float x) {
    float r;
    asm("ex2.approx.ftz.f32 %0, %1;" : "=f"(r) : "f"(x));
    return r;
}

__global__ __launch_bounds__(BLOCK, 1)
void su2_attn_kernel(const float* __restrict__ p0,   // spinors_real
                     const float* __restrict__ p1,   // spinors_imag
                     float* __restrict__ out) {
    // Dynamic shared (176 KB):
    //   sud:  SEQ x 2 float4, duplicated unit vecs (x,x,y,y),(z,z,w,w) (64 KB)
    //   sv:   SEQ float4 raw vectors                                   (32 KB)
    //   pacc: NWARP x QTILE float4 partials                            (64 KB)
    //   pden: NWARP x QTILE float partials                             (16 KB)
    extern __shared__ float4 smem[];
    float4* sud  = smem;                                  // [2*SEQ]
    float4* sv   = smem + 2 * SEQ;                        // [SEQ]
    float4* pacc = smem + 3 * SEQ;                        // [NWARP][QTILE]
    float*  pden = reinterpret_cast<float*>(pacc + NWARP * QTILE);

    const int h    = blockIdx.y;
    const int q0   = blockIdx.x * QTILE;
    const int lane = threadIdx.x & 31;
    const int warp = threadIdx.x >> 5;

    // Cooperative load + normalize of all SEQ vectors for this head.
    for (int j = threadIdx.x; j < SEQ; j += BLOCK) {
        const int base = (j * HEADS + h) * 2;
        float2 a = *reinterpret_cast<const float2*>(p0 + base);  // real (d0,d1)
        float2 b = *reinterpret_cast<const float2*>(p1 + base);  // imag (d0,d1)
        float x = a.x, y = a.y, z = b.x, w = b.y;
        float n2 = x*x + y*y + z*z + w*w;
        float rn = rsqrtf(n2);
        sv[j] = make_float4(x, y, z, w);
        float ux = x * rn, uy = y * rn, uz = z * rn, uw = w * rn;
        sud[2*j]   = make_float4(ux, ux, uy, uy);
        sud[2*j+1] = make_float4(uz, uz, uw, uw);
    }
    __syncthreads();

    // Each thread owns NQ=4 queries (2 pairs): q = q0 + lane + 32*i.
    // Pair p covers i = 2p, 2p+1. Fold SCALE*log2(e) into the query.
    const float C = 0.70710678118654752f * 1.44269504088896341f;
    float2 qpx[2], qpy[2], qpz[2], qpw[2];
    #pragma unroll
    for (int p = 0; p < 2; ++p) {
        const int base = (q0 + lane + 64 * p) * HEADS + h;
        // recompute unit q from raw sv (avoids unpacking sud)
        float4 sa = sv[q0 + lane + 64 * p];
        float4 sb = sv[q0 + lane + 64 * p + 32];
        float rna = rsqrtf(sa.x*sa.x + sa.y*sa.y + sa.z*sa.z + sa.w*sa.w) * C;
        float rnb = rsqrtf(sb.x*sb.x + sb.y*sb.y + sb.z*sb.z + sb.w*sb.w) * C;
        qpx[p] = make_float2(sa.x * rna, sb.x * rnb);
        qpy[p] = make_float2(sa.y * rna, sb.y * rnb);
        qpz[p] = make_float2(sa.z * rna, sb.z * rnb);
        qpw[p] = make_float2(sa.w * rna, sb.w * rnb);
        (void)base;
    }

    float2 acc01[NQ], acc23[NQ];
    float  den[NQ];
    #pragma unroll
    for (int i = 0; i < NQ; ++i) {
        acc01[i] = make_float2(0.f, 0.f);
        acc23[i] = make_float2(0.f, 0.f);
        den[i] = 0.f;
    }

    const int jlo = warp * JCHUNK;
    #pragma unroll 4
    for (int j = jlo; j < jlo + JCHUNK; ++j) {
        float4 uxy = sud[2*j];                 // (ux,ux,uy,uy)
        float4 uzw = sud[2*j+1];               // (uz,uz,uw,uw)
        float4 v   = sv[j];
        float2 uxx = make_float2(uxy.x, uxy.y);
        float2 uyy = make_float2(uxy.z, uxy.w);
        float2 uzz = make_float2(uzw.x, uzw.y);
        float2 uww = make_float2(uzw.z, uzw.w);
        float2 v01 = make_float2(v.x, v.y);
        float2 v23 = make_float2(v.z, v.w);

        // packed dots: t[p] = (dot for query 2p, dot for query 2p+1)
        float2 t0 = fmul2(qpx[0], uxx);
        float2 t1 = fmul2(qpx[1], uxx);
        t0 = ffma2(qpy[0], uyy, t0);
        t1 = ffma2(qpy[1], uyy, t1);
        t0 = ffma2(qpz[0], uzz, t0);
        t1 = ffma2(qpz[1], uzz, t1);
        t0 = ffma2(qpw[0], uww, t0);
        t1 = ffma2(qpw[1], uww, t1);

        float e0 = ex2_approx(t0.x);
        float e1 = ex2_approx(t0.y);
        float e2 = ex2_approx(t1.x);
        float e3 = ex2_approx(t1.y);

        float2 ee;
        ee = make_float2(e0, e0);
        acc01[0] = ffma2(ee, v01, acc01[0]);
        acc23[0] = ffma2(ee, v23, acc23[0]);
        ee = make_float2(e1, e1);
        acc01[1] = ffma2(ee, v01, acc01[1]);
        acc23[1] = ffma2(ee, v23, acc23[1]);
        ee = make_float2(e2, e2);
        acc01[2] = ffma2(ee, v01, acc01[2]);
        acc23[2] = ffma2(ee, v23, acc23[2]);
        ee = make_float2(e3, e3);
        acc01[3] = ffma2(ee, v01, acc01[3]);
        acc23[3] = ffma2(ee, v23, acc23[3]);
        den[0] += e0;
        den[1] += e1;
        den[2] += e2;
        den[3] += e3;
    }

    // Write per-warp partials. Query for (pair p, half b): lane + 64p + 32b
    // maps to old index i where i = 2p + b -> q = lane + 32*(2p+b)... careful:
    // pair p holds queries (q0+lane+64p, q0+lane+64p+32) = i indices (2p, 2p+1)
    #pragma unroll
    for (int p = 0; p < 2; ++p) {
        #pragma unroll
        for (int b = 0; b < 2; ++b) {
            const int i = 2 * p + b;
            const int q = lane + 64 * p + 32 * b;
            pacc[warp * QTILE + q] = make_float4(acc01[i].x, acc01[i].y,
                                                 acc23[i].x, acc23[i].y);
            pden[warp * QTILE + q] = den[i];
        }
    }
    __syncthreads();

    // Stage A: 8 groups of 4 splits -> 8 partials per query.
    {
        const int q = threadIdx.x & (QTILE - 1);
        const int g = threadIdx.x >> 7;              // 0..7
        const int s0 = g * 4;
        float4 a = pacc[s0 * QTILE + q];
        float  d = pden[s0 * QTILE + q];
        #pragma unroll
        for (int s = 1; s < 4; ++s) {
            float4 b = pacc[(s0 + s) * QTILE + q];
            a.x += b.x; a.y += b.y; a.z += b.z; a.w += b.w;
            d += pden[(s0 + s) * QTILE + q];
        }
        __syncthreads();
        pacc[s0 * QTILE + q] = a;
        pden[s0 * QTILE + q] = d;
    }
    __syncthreads();

    // Stage B: 128 threads finish the 8-way sum, normalize, store planar.
    if (threadIdx.x < QTILE) {
        const int q = threadIdx.x;
        float4 a = pacc[q];
        float  d = pden[q];
        #pragma unroll
        for (int g = 1; g < 8; ++g) {
            float4 b = pacc[g * 4 * QTILE + q];
            a.x += b.x; a.y += b.y; a.z += b.z; a.w += b.w;
            d += pden[g * 4 * QTILE + q];
        }
        const float inv = __frcp_rn(d);
        const int ohd = (q0 + q) * HEADS + h;
        // planar complex: real plane then imag plane, each (1,2048,8,2)
        *reinterpret_cast<float2*>(out + ohd * 2) =
            make_float2(a.x * inv, a.y * inv);
        *reinterpret_cast<float2*>(out + SEQ * HEADS * 2 + ohd * 2) =
            make_float2(a.z * inv, a.w * inv);
    }
}

extern "C" void kernel_launch(void* const* d_in, const int* in_sizes, int n_in,
                              void* d_out, int out_size) {
    const float* p0 = (const float*)d_in[0];
    const float* p1 = (const float*)d_in[1];
    float* out = (float*)d_out;

    const int shmem = 3 * SEQ * sizeof(float4)              // sud + sv
                    + NWARP * QTILE * sizeof(float4)        // pacc
                    + NWARP * QTILE * sizeof(float);        // pden
    cudaFuncSetAttribute(su2_attn_kernel,
                         cudaFuncAttributeMaxDynamicSharedMemorySize, shmem);

    dim3 grid(SEQ / QTILE, HEADS);
    dim3 block(BLOCK);
    su2_attn_kernel<<<grid, block, shmem>>>(p0, p1, out);
}